// round 16
// baseline (speedup 1.0000x reference)
#include <cuda_runtime.h>
#include <cuda_fp16.h>
#include <cstdint>

#define EPSV 1e-5f

// ---------------------------------------------------------------------------
// Scratch
// ---------------------------------------------------------------------------
__device__ __align__(16) __half g_xT [4LL * 4096 * 512];   // xT: [b][n][c] fp16
__device__ __align__(16) __half g_wh [655360];             // converted weights
__device__ __align__(16) __half g_hk [4LL * 4096 * 256];   // h_k: [n][c]
__device__ __align__(16) __half g_hq [4LL * 4096 * 256];   // h_q: [n][c]
__device__ __align__(16) __half g_K  [4LL * 4096 * 256];   // Kt:  [n][ck]
__device__ __align__(16) __half g_Q  [4LL * 4096 * 256];   // Qt:  [n][ck]
__device__ __align__(16) __half g_V  [4LL * 256 * 4096];   // V:   [c][n]
__device__ __align__(16) __half g_ctx[4LL * 4096 * 256];   // ctxT:[n][c]

// weight buffer layout (half elements)
#define W1S 0
#define W2S 393216
#define WOW 524288

// ---------------------------------------------------------------------------
// PTX helpers
// ---------------------------------------------------------------------------
__device__ __forceinline__ uint32_t smem_u32(const void* p) {
    uint32_t a;
    asm("{ .reg .u64 t; cvta.to.shared.u64 t, %1; cvt.u32.u64 %0, t; }" : "=r"(a) : "l"(p));
    return a;
}
#define CP_ASYNC16(dst, src) \
    asm volatile("cp.async.cg.shared.global [%0], [%1], 16;" :: "r"(dst), "l"(src))
#define CP_COMMIT() asm volatile("cp.async.commit_group;" ::: "memory")
#define CP_WAIT2()  asm volatile("cp.async.wait_group 2;"  ::: "memory")
#define CP_WAIT0()  asm volatile("cp.async.wait_group 0;"  ::: "memory")

__device__ __forceinline__ void ldsm_x4(uint32_t& r0, uint32_t& r1, uint32_t& r2,
                                        uint32_t& r3, uint32_t addr) {
    asm volatile("ldmatrix.sync.aligned.m8n8.x4.shared.b16 {%0,%1,%2,%3}, [%4];"
                 : "=r"(r0), "=r"(r1), "=r"(r2), "=r"(r3) : "r"(addr));
}
__device__ __forceinline__ void mma_f16(float* d, const uint32_t* a, const uint32_t* b) {
    asm volatile(
        "mma.sync.aligned.m16n8k16.row.col.f32.f16.f16.f32 "
        "{%0,%1,%2,%3}, {%4,%5,%6,%7}, {%8,%9}, {%0,%1,%2,%3};"
        : "+f"(d[0]), "+f"(d[1]), "+f"(d[2]), "+f"(d[3])
        : "r"(a[0]), "r"(a[1]), "r"(a[2]), "r"(a[3]),
          "r"(b[0]), "r"(b[1]));
}
__device__ __forceinline__ float ex2f(float x) {
    float r;
    asm("ex2.approx.f32 %0, %1;" : "=f"(r) : "f"(x));
    return r;
}
// exp(acc*0.0625 - 3) = ex2(acc*C1 + C0)
#define EXP_C1 0.09016844f
#define EXP_C0 -4.32808512f

// ---------------------------------------------------------------------------
// Preprocessing
// ---------------------------------------------------------------------------
__global__ void wconv_kernel(const float* __restrict__ kw1, const float* __restrict__ kw2,
                             const float* __restrict__ qw1, const float* __restrict__ qw2,
                             const float* __restrict__ vw,  const float* __restrict__ ow,
                             __half* __restrict__ d)
{
    int i = (blockIdx.x * blockDim.x + threadIdx.x) * 4;
    if (i >= 655360) return;
    const float* s; int off;
    if      (i < 131072) { s = kw1; off = i; }
    else if (i < 262144) { s = qw1; off = i - 131072; }
    else if (i < 393216) { s = vw;  off = i - 262144; }
    else if (i < 458752) { s = kw2; off = i - 393216; }
    else if (i < 524288) { s = qw2; off = i - 458752; }
    else                 { s = ow;  off = i - 524288; }
    float4 v = *(const float4*)(s + off);
    *(__half2*)(d + i)     = __floats2half2_rn(v.x, v.y);
    *(__half2*)(d + i + 2) = __floats2half2_rn(v.z, v.w);
}

// x [4][512][4096] fp32 -> xT [4][4096][512] fp16
__global__ void xT_kernel(const float* __restrict__ x, __half* __restrict__ xT)
{
    __shared__ float t[32][33];
    const int n0 = blockIdx.x * 32, c0 = blockIdx.y * 32;
    const long long b = blockIdx.z;
    const float* xb = x + (b * 512 + c0) * 4096 + n0;
#pragma unroll
    for (int j = 0; j < 32; j += 8)
        t[threadIdx.y + j][threadIdx.x] = xb[(long long)(threadIdx.y + j) * 4096 + threadIdx.x];
    __syncthreads();
    __half* dst = xT + (b * 4096 + n0) * 512 + c0;
#pragma unroll
    for (int j = 0; j < 32; j += 8)
        dst[(long long)(threadIdx.y + j) * 512 + threadIdx.x] =
            __float2half_rn(t[threadIdx.x][threadIdx.y + j]);
}

// ---------------------------------------------------------------------------
// Shared mainloop macro (8-warp, 128x128 tile, BK=32, 4-stage cp.async)
// ---------------------------------------------------------------------------
#define GEMM_MAINLOOP(Aptr, ldA, Bptr, ldB, KDIM)                              \
    const int crow = tid >> 2;                                                 \
    const int cq   = tid & 3;                                                  \
    auto issue = [&](int s, int c) {                                           \
        const int k0 = c << 5;                                                 \
        const uint32_t st = sb + s * 20480;                                    \
        _Pragma("unroll")                                                      \
        for (int i = 0; i < 2; ++i) {                                          \
            const int row = i * 64 + crow;                                     \
            CP_ASYNC16(st + row * 80 + cq * 16,                                \
                       Aptr + (long long)row * ldA + k0 + cq * 8);             \
            CP_ASYNC16(st + 10240 + row * 80 + cq * 16,                        \
                       Bptr + (long long)row * ldB + k0 + cq * 8);             \
        }                                                                      \
    };                                                                         \
    float acc[4][4][4];                                                        \
    _Pragma("unroll")                                                          \
    for (int i = 0; i < 4; ++i)                                                \
        _Pragma("unroll")                                                      \
        for (int j = 0; j < 4; ++j)                                            \
            _Pragma("unroll")                                                  \
            for (int r = 0; r < 4; ++r) acc[i][j][r] = 0.f;                    \
    const int NCH = (KDIM) >> 5;                                               \
    issue(0, 0); CP_COMMIT();                                                  \
    issue(1, 1); CP_COMMIT();                                                  \
    issue(2, 2); CP_COMMIT();                                                  \
    const uint32_t aoff = (wm * 64 + (lane & 15)) * 80 + (lane >> 4) * 16;     \
    const uint32_t boff = 10240 + (wn * 32 + (lane & 7) + ((lane >> 4) << 3)) * 80 \
                        + ((lane >> 3) & 1) * 16;                              \
    for (int c = 0; c < NCH; ++c) {                                            \
        CP_WAIT2();                                                            \
        __syncthreads();                                                       \
        const uint32_t st = sb + (c & 3) * 20480;                              \
        uint32_t a0[4][4], b0[4][2];                                           \
        _Pragma("unroll")                                                      \
        for (int i = 0; i < 4; ++i)                                            \
            ldsm_x4(a0[i][0], a0[i][1], a0[i][2], a0[i][3],                    \
                    st + aoff + i * 1280);                                     \
        _Pragma("unroll")                                                      \
        for (int p = 0; p < 2; ++p) {                                          \
            uint32_t t0, t1, t2, t3;                                           \
            ldsm_x4(t0, t1, t2, t3, st + boff + p * 1280);                     \
            b0[2 * p][0] = t0; b0[2 * p][1] = t1;                              \
            b0[2 * p + 1][0] = t2; b0[2 * p + 1][1] = t3;                      \
        }                                                                      \
        if (c + 3 < NCH) issue((c + 3) & 3, c + 3);                            \
        CP_COMMIT();                                                           \
        _Pragma("unroll")                                                      \
        for (int i = 0; i < 4; ++i)                                            \
            _Pragma("unroll")                                                  \
            for (int j = 0; j < 4; ++j)                                        \
                mma_f16(acc[i][j], a0[i], b0[j]);                              \
        uint32_t a1[4][4], b1[4][2];                                           \
        _Pragma("unroll")                                                      \
        for (int i = 0; i < 4; ++i)                                            \
            ldsm_x4(a1[i][0], a1[i][1], a1[i][2], a1[i][3],                    \
                    st + aoff + i * 1280 + 32);                                \
        _Pragma("unroll")                                                      \
        for (int p = 0; p < 2; ++p) {                                          \
            uint32_t t0, t1, t2, t3;                                           \
            ldsm_x4(t0, t1, t2, t3, st + boff + p * 1280 + 32);                \
            b1[2 * p][0] = t0; b1[2 * p][1] = t1;                              \
            b1[2 * p + 1][0] = t2; b1[2 * p + 1][1] = t3;                      \
        }                                                                      \
        _Pragma("unroll")                                                      \
        for (int i = 0; i < 4; ++i)                                            \
            _Pragma("unroll")                                                  \
            for (int j = 0; j < 4; ++j)                                        \
                mma_f16(acc[i][j], a1[i], b1[j]);                              \
    }

// ---------------------------------------------------------------------------
// proj1: one launch for k_w1 / q_w1 / v_w on shared B = xT.
// ---------------------------------------------------------------------------
__global__ void __launch_bounds__(256, 2)
proj1_kernel(const __half* __restrict__ wh, const __half* __restrict__ xT,
             __half* __restrict__ hk, __half* __restrict__ hq, __half* __restrict__ V,
             const float* __restrict__ kb, const float* __restrict__ kg,
             const float* __restrict__ kbe, const float* __restrict__ kmu,
             const float* __restrict__ kvr,
             const float* __restrict__ qb, const float* __restrict__ qg,
             const float* __restrict__ qbe, const float* __restrict__ qmu,
             const float* __restrict__ qvr,
             const float* __restrict__ vb)
{
    extern __shared__ char sm[];
    const uint32_t sb = smem_u32(sm);
    const int tid = threadIdx.x, lane = tid & 31, wid = tid >> 5;
    const int wm = wid >> 2, wn = wid & 3;
    const int m0 = blockIdx.y * 128, n0 = blockIdx.x * 128;
    const long long bz = blockIdx.z;
    const int sel = blockIdx.y >> 1;          // 0=k, 1=q, 2=v
    const int mloc0 = m0 - sel * 256;         // 0 or 128

    const __half* A = wh + W1S + (long long)m0 * 512;
    const __half* B = xT + bz * (4096LL * 512) + (long long)n0 * 512;

    GEMM_MAINLOOP(A, 512, B, 512, 512)

    const int g = lane >> 2, q4 = lane & 3;
    const float* bias = (sel == 0) ? kb : (sel == 1) ? qb : vb;

    if (sel < 2) {
        const float* gam = (sel == 0) ? kg  : qg;
        const float* bet = (sel == 0) ? kbe : qbe;
        const float* mu  = (sel == 0) ? kmu : qmu;
        const float* var = (sel == 0) ? kvr : qvr;
        __half* out = ((sel == 0) ? hk : hq) + bz * (4096LL * 256);
#pragma unroll
        for (int i = 0; i < 4; ++i) {
            const int mA = mloc0 + wm * 64 + i * 16 + g;
            const int mB = mA + 8;
            const float bA = bias[mA], bB = bias[mB];
            const float sA = gam[mA] * rsqrtf(var[mA] + EPSV);
            const float tA = bet[mA] - mu[mA] * sA;
            const float sB = gam[mB] * rsqrtf(var[mB] + EPSV);
            const float tB = bet[mB] - mu[mB] * sB;
#pragma unroll
            for (int j = 0; j < 4; ++j) {
                const int col = n0 + wn * 32 + j * 8 + q4 * 2;
                float v00 = fmaxf(fmaf(acc[i][j][0] + bA, sA, tA), 0.f);
                float v01 = fmaxf(fmaf(acc[i][j][1] + bA, sA, tA), 0.f);
                float v10 = fmaxf(fmaf(acc[i][j][2] + bB, sB, tB), 0.f);
                float v11 = fmaxf(fmaf(acc[i][j][3] + bB, sB, tB), 0.f);
                out[(long long)col * 256 + mA]       = __float2half_rn(v00);
                out[(long long)(col + 1) * 256 + mA] = __float2half_rn(v01);
                out[(long long)col * 256 + mB]       = __float2half_rn(v10);
                out[(long long)(col + 1) * 256 + mB] = __float2half_rn(v11);
            }
        }
    } else {
        __half* out = V + bz * (4096LL * 256);
#pragma unroll
        for (int i = 0; i < 4; ++i) {
            const int mA = mloc0 + wm * 64 + i * 16 + g;
            const int mB = mA + 8;
            const float bA = bias[mA], bB = bias[mB];
#pragma unroll
            for (int j = 0; j < 4; ++j) {
                const int col = n0 + wn * 32 + j * 8 + q4 * 2;
                *(__half2*)&out[(long long)mA * 4096 + col] =
                    __floats2half2_rn(acc[i][j][0] + bA, acc[i][j][1] + bA);
                *(__half2*)&out[(long long)mB * 4096 + col] =
                    __floats2half2_rn(acc[i][j][2] + bB, acc[i][j][3] + bB);
            }
        }
    }
}

// ---------------------------------------------------------------------------
// proj2: one launch for k_w2 . h_k and q_w2 . h_q (block-diagonal).
// ---------------------------------------------------------------------------
__global__ void __launch_bounds__(256, 2)
proj2_kernel(const __half* __restrict__ wh,
             const __half* __restrict__ hk, const __half* __restrict__ hq,
             __half* __restrict__ Kt, __half* __restrict__ Qt,
             const float* __restrict__ kb, const float* __restrict__ kg,
             const float* __restrict__ kbe, const float* __restrict__ kmu,
             const float* __restrict__ kvr,
             const float* __restrict__ qb, const float* __restrict__ qg,
             const float* __restrict__ qbe, const float* __restrict__ qmu,
             const float* __restrict__ qvr)
{
    extern __shared__ char sm[];
    const uint32_t sb = smem_u32(sm);
    const int tid = threadIdx.x, lane = tid & 31, wid = tid >> 5;
    const int wm = wid >> 2, wn = wid & 3;
    const int m0 = blockIdx.y * 128, n0 = blockIdx.x * 128;
    const long long bz = blockIdx.z;
    const int sel = blockIdx.y >> 1;          // 0=k, 1=q
    const int mloc0 = m0 - sel * 256;

    const __half* A = wh + W2S + (long long)m0 * 256;
    const __half* B = ((sel == 0) ? hk : hq) + bz * (4096LL * 256)
                    + (long long)n0 * 256;

    GEMM_MAINLOOP(A, 256, B, 256, 256)

    const int g = lane >> 2, q4 = lane & 3;
    const float* bias = (sel == 0) ? kb  : qb;
    const float* gam  = (sel == 0) ? kg  : qg;
    const float* bet  = (sel == 0) ? kbe : qbe;
    const float* mu   = (sel == 0) ? kmu : qmu;
    const float* var  = (sel == 0) ? kvr : qvr;
    __half* out = ((sel == 0) ? Kt : Qt) + bz * (4096LL * 256);

#pragma unroll
    for (int i = 0; i < 4; ++i) {
        const int mA = mloc0 + wm * 64 + i * 16 + g;
        const int mB = mA + 8;
        const float bA = bias[mA], bB = bias[mB];
        const float sA = gam[mA] * rsqrtf(var[mA] + EPSV);
        const float tA = bet[mA] - mu[mA] * sA;
        const float sB = gam[mB] * rsqrtf(var[mB] + EPSV);
        const float tB = bet[mB] - mu[mB] * sB;
#pragma unroll
        for (int j = 0; j < 4; ++j) {
            const int col = n0 + wn * 32 + j * 8 + q4 * 2;
            float v00 = fmaxf(fmaf(acc[i][j][0] + bA, sA, tA), 0.f);
            float v01 = fmaxf(fmaf(acc[i][j][1] + bA, sA, tA), 0.f);
            float v10 = fmaxf(fmaf(acc[i][j][2] + bB, sB, tB), 0.f);
            float v11 = fmaxf(fmaf(acc[i][j][3] + bB, sB, tB), 0.f);
            out[(long long)col * 256 + mA]       = __float2half_rn(v00);
            out[(long long)(col + 1) * 256 + mA] = __float2half_rn(v01);
            out[(long long)col * 256 + mB]       = __float2half_rn(v10);
            out[(long long)(col + 1) * 256 + mB] = __float2half_rn(v11);
        }
    }
}

// ---------------------------------------------------------------------------
// out projection: out[co][n] = o_w . ctx + o_b  (fp32 out)
// ---------------------------------------------------------------------------
__global__ void __launch_bounds__(256, 2)
outp_kernel(const __half* __restrict__ wh, const __half* __restrict__ ctx,
            float* __restrict__ out, const float* __restrict__ bias)
{
    extern __shared__ char sm[];
    const uint32_t sb = smem_u32(sm);
    const int tid = threadIdx.x, lane = tid & 31, wid = tid >> 5;
    const int wm = wid >> 2, wn = wid & 3;
    const int m0 = blockIdx.y * 128, n0 = blockIdx.x * 128;
    const long long bz = blockIdx.z;

    const __half* A = wh + WOW + (long long)m0 * 256;
    const __half* B = ctx + bz * (4096LL * 256) + (long long)n0 * 256;

    GEMM_MAINLOOP(A, 256, B, 256, 256)

    const int g = lane >> 2, q4 = lane & 3;
    float* og = out + bz * (512LL * 4096);
#pragma unroll
    for (int i = 0; i < 4; ++i) {
        const int mA = m0 + wm * 64 + i * 16 + g;
        const int mB = mA + 8;
        const float bA = bias[mA], bB = bias[mB];
#pragma unroll
        for (int j = 0; j < 4; ++j) {
            const int col = n0 + wn * 32 + j * 8 + q4 * 2;
            *(float2*)&og[(long long)mA * 4096 + col] =
                make_float2(acc[i][j][0] + bA, acc[i][j][1] + bA);
            *(float2*)&og[(long long)mB * 4096 + col] =
                make_float2(acc[i][j][2] + bB, acc[i][j][3] + bB);
        }
    }
}

// ---------------------------------------------------------------------------
// Fused attention, 64 queries/CTA, 256 threads, 2 CTAs/SM (16 warps/SM).
// Warp tiles: phase A 32x32 (accS 32), phase B 32x64 (accO 64) — same
// fragment-traffic ratio as the proven 128q config.
// 2-slot ring, serial protocol: region i = [wait_group 0; sync;
// issue L_{i+1} into slot^1; compute slot]. slot^1's last reader finished
// at this region's barrier, so the overwrite is race-free.
// SMEM: Q 8x5120 | ring 2x20480 | P 4x5120 | rsum 256 = 102656 B
// ---------------------------------------------------------------------------
#define QS_OFF   0
#define RING_OFF 40960
#define PS_OFF   81920
#define RS_OFF   102400
#define ATT_SMEM 102656

__global__ void __launch_bounds__(256, 2)
attn_fused(const __half* __restrict__ Qt, const __half* __restrict__ Kt,
           const __half* __restrict__ Vf, __half* __restrict__ ctx)
{
    extern __shared__ char sm[];
    const uint32_t sb = smem_u32(sm);

    const int tid = threadIdx.x, lane = tid & 31, wid = tid >> 5;
    const int wm = wid >> 2, wn = wid & 3;
    const int g = lane >> 2, q4 = lane & 3;
    const int n0 = blockIdx.x * 64;            // 64-query block
    const long long bz = blockIdx.z;
    const long long sC = 4096LL * 256;

    const __half* Qg = Qt + bz * sC + (long long)n0 * 256;
    const __half* Kg = Kt + bz * sC;
    const __half* Vg = Vf + bz * sC;

    const int crow = tid >> 2, cq = tid & 3;   // 64 rows x 4 quads

    float* rsum = (float*)(sm + RS_OFF);
    if (tid < 64) rsum[tid] = 0.f;

    // 64-wide K chunk j (2 sections of 128 keys x 32 K) into ring slot s
    auto issueK64 = [&](int kt, int j, int s) {
        if (kt >= 32) return;
        const uint32_t st = sb + RING_OFF + s * 20480;
        const __half* src = Kg + (long long)(kt * 128) * 256 + j * 64;
#pragma unroll
        for (int sec = 0; sec < 2; ++sec)
#pragma unroll
            for (int i = 0; i < 2; ++i) {
                const int row = i * 64 + crow;
                CP_ASYNC16(st + sec * 10240 + row * 80 + cq * 16,
                           src + row * 256 + sec * 32 + cq * 8);
            }
    };
    // V chunk vc (256 ch x 32 keys) into ring slot s
    auto issueV = [&](int kt, int vc, int s) {
        const uint32_t st = sb + RING_OFF + s * 20480;
        const __half* src = Vg + kt * 128 + vc * 32;
#pragma unroll
        for (int i = 0; i < 4; ++i) {
            const int row = i * 64 + crow;
            CP_ASYNC16(st + row * 80 + cq * 16, src + (long long)row * 4096 + cq * 8);
        }
    };

    // ---- prologue: Q (64 rows x 256 K, 1 cp per thread per section) + A0 ----
#pragma unroll
    for (int c = 0; c < 8; ++c)
        CP_ASYNC16(sb + QS_OFF + c * 5120 + crow * 80 + cq * 16,
                   Qg + crow * 256 + c * 32 + cq * 8);
    CP_COMMIT();
    issueK64(0, 0, 0); CP_COMMIT();

    const uint32_t aoff  = (wm * 32 + (lane & 15)) * 80 + (lane >> 4) * 16;
    const uint32_t boffK = (wn * 32 + (lane & 7) + ((lane >> 4) << 3)) * 80
                         + ((lane >> 3) & 1) * 16;
    const uint32_t boffV = (wn * 64 + (lane & 7) + ((lane >> 4) << 3)) * 80
                         + ((lane >> 3) & 1) * 16;

    float accO[2][8][4];
#pragma unroll
    for (int i = 0; i < 2; ++i)
#pragma unroll
        for (int j = 0; j < 8; ++j)
#pragma unroll
            for (int r = 0; r < 4; ++r) accO[i][j][r] = 0.f;
    float rs[2][2];
    rs[0][0] = rs[0][1] = rs[1][0] = rs[1][1] = 0.f;

    int slot = 0;
    for (int kt = 0; kt < 32; ++kt) {
        // ============ phase A: S tile (4 regions, 64-wide K chunks) ========
        float accS[2][4][4];
#pragma unroll
        for (int i = 0; i < 2; ++i)
#pragma unroll
            for (int j = 0; j < 4; ++j)
#pragma unroll
                for (int r = 0; r < 4; ++r) accS[i][j][r] = 0.f;

#pragma unroll
        for (int j = 0; j < 4; ++j) {
            CP_WAIT0();
            __syncthreads();
            if (j < 3) issueK64(kt, j + 1, slot ^ 1);
            else       issueV(kt, 0, slot ^ 1);
            CP_COMMIT();

            const uint32_t st = sb + RING_OFF + slot * 20480;
#pragma unroll
            for (int sec = 0; sec < 2; ++sec) {
                const uint32_t qs = sb + QS_OFF + (2 * j + sec) * 5120;
                const uint32_t ks = st + sec * 10240;
#pragma unroll
                for (int k = 0; k < 2; ++k) {
                    uint32_t a[2][4], b[4][2];
#pragma unroll
                    for (int i = 0; i < 2; ++i)
                        ldsm_x4(a[i][0], a[i][1], a[i][2], a[i][3],
                                qs + aoff + i * 1280 + k * 32);
#pragma unroll
                    for (int p = 0; p < 2; ++p) {
                        uint32_t t0, t1, t2, t3;
                        ldsm_x4(t0, t1, t2, t3, ks + boffK + p * 1280 + k * 32);
                        b[2 * p][0] = t0; b[2 * p][1] = t1;
                        b[2 * p + 1][0] = t2; b[2 * p + 1][1] = t3;
                    }
#pragma unroll
                    for (int i = 0; i < 2; ++i)
#pragma unroll
                        for (int jj = 0; jj < 4; ++jj)
                            mma_f16(accS[i][jj], a[i], b[jj]);
                }
            }
            slot ^= 1;
        }

        // ---- exp -> P tile (SMEM), row-sum partials ----
        {
            char* pbase = sm + PS_OFF + wn * 5120;
#pragma unroll
            for (int i = 0; i < 2; ++i) {
                const int rA = wm * 32 + i * 16 + g;
                float sA = 0.f, sB = 0.f;
#pragma unroll
                for (int j = 0; j < 4; ++j) {
                    float v00 = ex2f(fmaf(accS[i][j][0], EXP_C1, EXP_C0));
                    float v01 = ex2f(fmaf(accS[i][j][1], EXP_C1, EXP_C0));
                    float v10 = ex2f(fmaf(accS[i][j][2], EXP_C1, EXP_C0));
                    float v11 = ex2f(fmaf(accS[i][j][3], EXP_C1, EXP_C0));
                    sA += v00 + v01; sB += v10 + v11;
                    const int bofs = j * 16 + q4 * 4;
                    *(__half2*)(pbase + rA * 80 + bofs)       = __floats2half2_rn(v00, v01);
                    *(__half2*)(pbase + (rA + 8) * 80 + bofs) = __floats2half2_rn(v10, v11);
                }
                rs[i][0] += sA; rs[i][1] += sB;
            }
        }

        // ============ phase B: accO += P . V^T (4 regions) ============
#pragma unroll
        for (int vc = 0; vc < 4; ++vc) {
            CP_WAIT0();
            __syncthreads();
            if (vc < 3) issueV(kt, vc + 1, slot ^ 1);
            else        issueK64(kt + 1, 0, slot ^ 1);
            CP_COMMIT();

            const uint32_t st = sb + RING_OFF + slot * 20480;
            const uint32_t ps = sb + PS_OFF + vc * 5120;
#pragma unroll
            for (int k = 0; k < 2; ++k) {
                uint32_t a[2][4], b[8][2];
#pragma unroll
                for (int i = 0; i < 2; ++i)
                    ldsm_x4(a[i][0], a[i][1], a[i][2], a[i][3],
                            ps + aoff + i * 1280 + k * 32);
#pragma unroll
                for (int p = 0; p < 4; ++p) {
                    uint32_t t0, t1, t2, t3;
                    ldsm_x4(t0, t1, t2, t3, st + boffV + p * 1280 + k * 32);
                    b[2 * p][0] = t0; b[2 * p][1] = t1;
                    b[2 * p + 1][0] = t2; b[2 * p + 1][1] = t3;
                }
#pragma unroll
                for (int i = 0; i < 2; ++i)
#pragma unroll
                    for (int j = 0; j < 8; ++j)
                        mma_f16(accO[i][j], a[i], b[j]);
            }
            slot ^= 1;
        }
    }

    // ---- row-sum reduce across warps ----
#pragma unroll
    for (int i = 0; i < 2; ++i) {
        float sA = rs[i][0], sB = rs[i][1];
        sA += __shfl_xor_sync(0xffffffffu, sA, 1);
        sA += __shfl_xor_sync(0xffffffffu, sA, 2);
        sB += __shfl_xor_sync(0xffffffffu, sB, 1);
        sB += __shfl_xor_sync(0xffffffffu, sB, 2);
        if (q4 == 0) {
            atomicAdd(&rsum[wm * 32 + i * 16 + g], sA);
            atomicAdd(&rsum[wm * 32 + i * 16 + g + 8], sB);
        }
    }
    __syncthreads();

    // ---- normalize + store ctx [n][c] ----
    __half* cg = ctx + (bz * 4096 + n0) * 256;
#pragma unroll
    for (int i = 0; i < 2; ++i) {
        const int rA = wm * 32 + i * 16 + g;
        const float iA = 1.f / rsum[rA];
        const float iB = 1.f / rsum[rA + 8];
#pragma unroll
        for (int j = 0; j < 8; ++j) {
            const int col = wn * 64 + j * 8 + q4 * 2;
            *(__half2*)&cg[(long long)rA * 256 + col] =
                __floats2half2_rn(accO[i][j][0] * iA, accO[i][j][1] * iA);
            *(__half2*)&cg[(long long)(rA + 8) * 256 + col] =
                __floats2half2_rn(accO[i][j][2] * iB, accO[i][j][3] * iB);
        }
    }
}

// ---------------------------------------------------------------------------
extern "C" void kernel_launch(void* const* d_in, const int* in_sizes, int n_in,
                              void* d_out, int out_size)
{
    const float* x     = (const float*)d_in[0];
    const float* k_w1  = (const float*)d_in[1];
    const float* k_b1  = (const float*)d_in[2];
    const float* k_g1  = (const float*)d_in[3];
    const float* k_be1 = (const float*)d_in[4];
    const float* k_m1  = (const float*)d_in[5];
    const float* k_v1  = (const float*)d_in[6];
    const float* k_w2  = (const float*)d_in[7];
    const float* k_b2  = (const float*)d_in[8];
    const float* k_g2  = (const float*)d_in[9];
    const float* k_be2 = (const float*)d_in[10];
    const float* k_m2  = (const float*)d_in[11];
    const float* k_v2  = (const float*)d_in[12];
    const float* q_w1  = (const float*)d_in[13];
    const float* q_b1  = (const float*)d_in[14];
    const float* q_g1  = (const float*)d_in[15];
    const float* q_be1 = (const float*)d_in[16];
    const float* q_m1  = (const float*)d_in[17];
    const float* q_v1  = (const float*)d_in[18];
    const float* q_w2  = (const float*)d_in[19];
    const float* q_b2  = (const float*)d_in[20];
    const float* q_g2  = (const float*)d_in[21];
    const float* q_be2 = (const float*)d_in[22];
    const float* q_m2  = (const float*)d_in[23];
    const float* q_v2  = (const float*)d_in[24];
    const float* v_w   = (const float*)d_in[25];
    const float* v_b   = (const float*)d_in[26];
    const float* o_w   = (const float*)d_in[27];
    const float* o_b   = (const float*)d_in[28];

    void *xT_, *wh_, *hk_, *hq_, *Kt_, *Qt_, *V_, *ctx_;
    cudaGetSymbolAddress(&xT_,  g_xT);
    cudaGetSymbolAddress(&wh_,  g_wh);
    cudaGetSymbolAddress(&hk_,  g_hk);
    cudaGetSymbolAddress(&hq_,  g_hq);
    cudaGetSymbolAddress(&Kt_,  g_K);
    cudaGetSymbolAddress(&Qt_,  g_Q);
    cudaGetSymbolAddress(&V_,   g_V);
    cudaGetSymbolAddress(&ctx_, g_ctx);
    __half* xT  = (__half*)xT_;
    __half* wh  = (__half*)wh_;
    __half* hk  = (__half*)hk_;
    __half* hq  = (__half*)hq_;
    __half* Kt  = (__half*)Kt_;
    __half* Qt  = (__half*)Qt_;
    __half* V   = (__half*)V_;
    __half* ctx = (__half*)ctx_;

    const int GSM = 81920;
    cudaFuncSetAttribute(proj1_kernel, cudaFuncAttributeMaxDynamicSharedMemorySize, GSM);
    cudaFuncSetAttribute(proj2_kernel, cudaFuncAttributeMaxDynamicSharedMemorySize, GSM);
    cudaFuncSetAttribute(outp_kernel,  cudaFuncAttributeMaxDynamicSharedMemorySize, GSM);
    cudaFuncSetAttribute(attn_fused,   cudaFuncAttributeMaxDynamicSharedMemorySize, ATT_SMEM);

    // ---- preprocessing ----
    wconv_kernel<<<640, 256>>>(k_w1, k_w2, q_w1, q_w2, v_w, o_w, wh);
    xT_kernel<<<dim3(128, 16, 4), dim3(32, 8)>>>(x, xT);

    // ---- stage 1: h_k, h_q, V in ONE launch ----
    proj1_kernel<<<dim3(32, 6, 4), 256, GSM>>>(
        wh, xT, hk, hq, V,
        k_b1, k_g1, k_be1, k_m1, k_v1,
        q_b1, q_g1, q_be1, q_m1, q_v1,
        v_b);
    // ---- stage 2: Kt, Qt in ONE launch ----
    proj2_kernel<<<dim3(32, 4, 4), 256, GSM>>>(
        wh, hk, hq, Kt, Qt,
        k_b2, k_g2, k_be2, k_m2, k_v2,
        q_b2, q_g2, q_be2, q_m2, q_v2);
    // ---- fused attention: 64-query CTAs, 2 CTAs/SM ----
    attn_fused<<<dim3(64, 1, 4), 256, ATT_SMEM>>>(Qt, Kt, V, ctx);
    // ---- output projection ----
    outp_kernel<<<dim3(32, 4, 4), 256, GSM>>>(wh, ctx, (float*)d_out, o_b);
}

// round 17
// speedup vs baseline: 1.2362x; 1.2362x over previous
#include <cuda_runtime.h>
#include <cuda_fp16.h>
#include <cstdint>

#define EPSV 1e-5f

// ---------------------------------------------------------------------------
// Scratch
// ---------------------------------------------------------------------------
__device__ __align__(16) __half g_xT [4LL * 4096 * 512];   // xT: [b][n][c] fp16
__device__ __align__(16) __half g_wh [655360];             // converted weights
__device__ __align__(16) __half g_hk [4LL * 4096 * 256];   // h_k: [n][c]
__device__ __align__(16) __half g_hq [4LL * 4096 * 256];   // h_q: [n][c]
__device__ __align__(16) __half g_K  [4LL * 4096 * 256];   // Kt:  [n][ck]
__device__ __align__(16) __half g_Q  [4LL * 4096 * 256];   // Qt:  [n][ck]
__device__ __align__(16) __half g_V  [4LL * 256 * 4096];   // V:   [c][n]
__device__ __align__(16) __half g_ctx[4LL * 4096 * 256];   // ctxT:[n][c]

// weight buffer layout (half elements)
#define W1S 0
#define W2S 393216
#define WOW 524288

// ---------------------------------------------------------------------------
// PTX helpers
// ---------------------------------------------------------------------------
__device__ __forceinline__ uint32_t smem_u32(const void* p) {
    uint32_t a;
    asm("{ .reg .u64 t; cvta.to.shared.u64 t, %1; cvt.u32.u64 %0, t; }" : "=r"(a) : "l"(p));
    return a;
}
#define CP_ASYNC16(dst, src) \
    asm volatile("cp.async.cg.shared.global [%0], [%1], 16;" :: "r"(dst), "l"(src))
#define CP_COMMIT() asm volatile("cp.async.commit_group;" ::: "memory")
#define CP_WAIT2()  asm volatile("cp.async.wait_group 2;"  ::: "memory")

__device__ __forceinline__ void ldsm_x4(uint32_t& r0, uint32_t& r1, uint32_t& r2,
                                        uint32_t& r3, uint32_t addr) {
    asm volatile("ldmatrix.sync.aligned.m8n8.x4.shared.b16 {%0,%1,%2,%3}, [%4];"
                 : "=r"(r0), "=r"(r1), "=r"(r2), "=r"(r3) : "r"(addr));
}
__device__ __forceinline__ void mma_f16(float* d, const uint32_t* a, const uint32_t* b) {
    asm volatile(
        "mma.sync.aligned.m16n8k16.row.col.f32.f16.f16.f32 "
        "{%0,%1,%2,%3}, {%4,%5,%6,%7}, {%8,%9}, {%0,%1,%2,%3};"
        : "+f"(d[0]), "+f"(d[1]), "+f"(d[2]), "+f"(d[3])
        : "r"(a[0]), "r"(a[1]), "r"(a[2]), "r"(a[3]),
          "r"(b[0]), "r"(b[1]));
}
__device__ __forceinline__ float ex2f(float x) {
    float r;
    asm("ex2.approx.f32 %0, %1;" : "=f"(r) : "f"(x));
    return r;
}
// exp(acc*0.0625 - 3) = ex2(acc*C1 + C0)
#define EXP_C1 0.09016844f
#define EXP_C0 -4.32808512f

// ---------------------------------------------------------------------------
// Preprocessing
// ---------------------------------------------------------------------------
__global__ void wconv_kernel(const float* __restrict__ kw1, const float* __restrict__ kw2,
                             const float* __restrict__ qw1, const float* __restrict__ qw2,
                             const float* __restrict__ vw,  const float* __restrict__ ow,
                             __half* __restrict__ d)
{
    int i = (blockIdx.x * blockDim.x + threadIdx.x) * 4;
    if (i >= 655360) return;
    const float* s; int off;
    if      (i < 131072) { s = kw1; off = i; }
    else if (i < 262144) { s = qw1; off = i - 131072; }
    else if (i < 393216) { s = vw;  off = i - 262144; }
    else if (i < 458752) { s = kw2; off = i - 393216; }
    else if (i < 524288) { s = qw2; off = i - 458752; }
    else                 { s = ow;  off = i - 524288; }
    float4 v = *(const float4*)(s + off);
    *(__half2*)(d + i)     = __floats2half2_rn(v.x, v.y);
    *(__half2*)(d + i + 2) = __floats2half2_rn(v.z, v.w);
}

// x [4][512][4096] fp32 -> xT [4][4096][512] fp16
__global__ void xT_kernel(const float* __restrict__ x, __half* __restrict__ xT)
{
    __shared__ float t[32][33];
    const int n0 = blockIdx.x * 32, c0 = blockIdx.y * 32;
    const long long b = blockIdx.z;
    const float* xb = x + (b * 512 + c0) * 4096 + n0;
#pragma unroll
    for (int j = 0; j < 32; j += 8)
        t[threadIdx.y + j][threadIdx.x] = xb[(long long)(threadIdx.y + j) * 4096 + threadIdx.x];
    __syncthreads();
    __half* dst = xT + (b * 4096 + n0) * 512 + c0;
#pragma unroll
    for (int j = 0; j < 32; j += 8)
        dst[(long long)(threadIdx.y + j) * 512 + threadIdx.x] =
            __float2half_rn(t[threadIdx.x][threadIdx.y + j]);
}

// ---------------------------------------------------------------------------
// Shared mainloop macro (8-warp, 128x128 tile, BK=32, 4-stage cp.async)
// ---------------------------------------------------------------------------
#define GEMM_MAINLOOP(Aptr, ldA, Bptr, ldB, KDIM)                              \
    const int crow = tid >> 2;                                                 \
    const int cq   = tid & 3;                                                  \
    auto issue = [&](int s, int c) {                                           \
        const int k0 = c << 5;                                                 \
        const uint32_t st = sb + s * 20480;                                    \
        _Pragma("unroll")                                                      \
        for (int i = 0; i < 2; ++i) {                                          \
            const int row = i * 64 + crow;                                     \
            CP_ASYNC16(st + row * 80 + cq * 16,                                \
                       Aptr + (long long)row * ldA + k0 + cq * 8);             \
            CP_ASYNC16(st + 10240 + row * 80 + cq * 16,                        \
                       Bptr + (long long)row * ldB + k0 + cq * 8);             \
        }                                                                      \
    };                                                                         \
    float acc[4][4][4];                                                        \
    _Pragma("unroll")                                                          \
    for (int i = 0; i < 4; ++i)                                                \
        _Pragma("unroll")                                                      \
        for (int j = 0; j < 4; ++j)                                            \
            _Pragma("unroll")                                                  \
            for (int r = 0; r < 4; ++r) acc[i][j][r] = 0.f;                    \
    const int NCH = (KDIM) >> 5;                                               \
    issue(0, 0); CP_COMMIT();                                                  \
    issue(1, 1); CP_COMMIT();                                                  \
    issue(2, 2); CP_COMMIT();                                                  \
    const uint32_t aoff = (wm * 64 + (lane & 15)) * 80 + (lane >> 4) * 16;     \
    const uint32_t boff = 10240 + (wn * 32 + (lane & 7) + ((lane >> 4) << 3)) * 80 \
                        + ((lane >> 3) & 1) * 16;                              \
    for (int c = 0; c < NCH; ++c) {                                            \
        CP_WAIT2();                                                            \
        __syncthreads();                                                       \
        const uint32_t st = sb + (c & 3) * 20480;                              \
        uint32_t a0[4][4], b0[4][2];                                           \
        _Pragma("unroll")                                                      \
        for (int i = 0; i < 4; ++i)                                            \
            ldsm_x4(a0[i][0], a0[i][1], a0[i][2], a0[i][3],                    \
                    st + aoff + i * 1280);                                     \
        _Pragma("unroll")                                                      \
        for (int p = 0; p < 2; ++p) {                                          \
            uint32_t t0, t1, t2, t3;                                           \
            ldsm_x4(t0, t1, t2, t3, st + boff + p * 1280);                     \
            b0[2 * p][0] = t0; b0[2 * p][1] = t1;                              \
            b0[2 * p + 1][0] = t2; b0[2 * p + 1][1] = t3;                      \
        }                                                                      \
        if (c + 3 < NCH) issue((c + 3) & 3, c + 3);                            \
        CP_COMMIT();                                                           \
        _Pragma("unroll")                                                      \
        for (int i = 0; i < 4; ++i)                                            \
            _Pragma("unroll")                                                  \
            for (int j = 0; j < 4; ++j)                                        \
                mma_f16(acc[i][j], a0[i], b0[j]);                              \
        uint32_t a1[4][4], b1[4][2];                                           \
        _Pragma("unroll")                                                      \
        for (int i = 0; i < 4; ++i)                                            \
            ldsm_x4(a1[i][0], a1[i][1], a1[i][2], a1[i][3],                    \
                    st + aoff + i * 1280 + 32);                                \
        _Pragma("unroll")                                                      \
        for (int p = 0; p < 2; ++p) {                                          \
            uint32_t t0, t1, t2, t3;                                           \
            ldsm_x4(t0, t1, t2, t3, st + boff + p * 1280 + 32);                \
            b1[2 * p][0] = t0; b1[2 * p][1] = t1;                              \
            b1[2 * p + 1][0] = t2; b1[2 * p + 1][1] = t3;                      \
        }                                                                      \
        _Pragma("unroll")                                                      \
        for (int i = 0; i < 4; ++i)                                            \
            _Pragma("unroll")                                                  \
            for (int j = 0; j < 4; ++j)                                        \
                mma_f16(acc[i][j], a1[i], b1[j]);                              \
    }

// ---------------------------------------------------------------------------
// proj1: one launch for k_w1 / q_w1 / v_w on shared B = xT.
// ---------------------------------------------------------------------------
__global__ void __launch_bounds__(256, 2)
proj1_kernel(const __half* __restrict__ wh, const __half* __restrict__ xT,
             __half* __restrict__ hk, __half* __restrict__ hq, __half* __restrict__ V,
             const float* __restrict__ kb, const float* __restrict__ kg,
             const float* __restrict__ kbe, const float* __restrict__ kmu,
             const float* __restrict__ kvr,
             const float* __restrict__ qb, const float* __restrict__ qg,
             const float* __restrict__ qbe, const float* __restrict__ qmu,
             const float* __restrict__ qvr,
             const float* __restrict__ vb)
{
    extern __shared__ char sm[];
    const uint32_t sb = smem_u32(sm);
    const int tid = threadIdx.x, lane = tid & 31, wid = tid >> 5;
    const int wm = wid >> 2, wn = wid & 3;
    const int m0 = blockIdx.y * 128, n0 = blockIdx.x * 128;
    const long long bz = blockIdx.z;
    const int sel = blockIdx.y >> 1;          // 0=k, 1=q, 2=v
    const int mloc0 = m0 - sel * 256;         // 0 or 128

    const __half* A = wh + W1S + (long long)m0 * 512;
    const __half* B = xT + bz * (4096LL * 512) + (long long)n0 * 512;

    GEMM_MAINLOOP(A, 512, B, 512, 512)

    const int g = lane >> 2, q4 = lane & 3;
    const float* bias = (sel == 0) ? kb : (sel == 1) ? qb : vb;

    if (sel < 2) {
        const float* gam = (sel == 0) ? kg  : qg;
        const float* bet = (sel == 0) ? kbe : qbe;
        const float* mu  = (sel == 0) ? kmu : qmu;
        const float* var = (sel == 0) ? kvr : qvr;
        __half* out = ((sel == 0) ? hk : hq) + bz * (4096LL * 256);
#pragma unroll
        for (int i = 0; i < 4; ++i) {
            const int mA = mloc0 + wm * 64 + i * 16 + g;
            const int mB = mA + 8;
            const float bA = bias[mA], bB = bias[mB];
            const float sA = gam[mA] * rsqrtf(var[mA] + EPSV);
            const float tA = bet[mA] - mu[mA] * sA;
            const float sB = gam[mB] * rsqrtf(var[mB] + EPSV);
            const float tB = bet[mB] - mu[mB] * sB;
#pragma unroll
            for (int j = 0; j < 4; ++j) {
                const int col = n0 + wn * 32 + j * 8 + q4 * 2;
                float v00 = fmaxf(fmaf(acc[i][j][0] + bA, sA, tA), 0.f);
                float v01 = fmaxf(fmaf(acc[i][j][1] + bA, sA, tA), 0.f);
                float v10 = fmaxf(fmaf(acc[i][j][2] + bB, sB, tB), 0.f);
                float v11 = fmaxf(fmaf(acc[i][j][3] + bB, sB, tB), 0.f);
                out[(long long)col * 256 + mA]       = __float2half_rn(v00);
                out[(long long)(col + 1) * 256 + mA] = __float2half_rn(v01);
                out[(long long)col * 256 + mB]       = __float2half_rn(v10);
                out[(long long)(col + 1) * 256 + mB] = __float2half_rn(v11);
            }
        }
    } else {
        __half* out = V + bz * (4096LL * 256);
#pragma unroll
        for (int i = 0; i < 4; ++i) {
            const int mA = mloc0 + wm * 64 + i * 16 + g;
            const int mB = mA + 8;
            const float bA = bias[mA], bB = bias[mB];
#pragma unroll
            for (int j = 0; j < 4; ++j) {
                const int col = n0 + wn * 32 + j * 8 + q4 * 2;
                *(__half2*)&out[(long long)mA * 4096 + col] =
                    __floats2half2_rn(acc[i][j][0] + bA, acc[i][j][1] + bA);
                *(__half2*)&out[(long long)mB * 4096 + col] =
                    __floats2half2_rn(acc[i][j][2] + bB, acc[i][j][3] + bB);
            }
        }
    }
}

// ---------------------------------------------------------------------------
// proj2: one launch for k_w2 . h_k and q_w2 . h_q (block-diagonal).
// ---------------------------------------------------------------------------
__global__ void __launch_bounds__(256, 2)
proj2_kernel(const __half* __restrict__ wh,
             const __half* __restrict__ hk, const __half* __restrict__ hq,
             __half* __restrict__ Kt, __half* __restrict__ Qt,
             const float* __restrict__ kb, const float* __restrict__ kg,
             const float* __restrict__ kbe, const float* __restrict__ kmu,
             const float* __restrict__ kvr,
             const float* __restrict__ qb, const float* __restrict__ qg,
             const float* __restrict__ qbe, const float* __restrict__ qmu,
             const float* __restrict__ qvr)
{
    extern __shared__ char sm[];
    const uint32_t sb = smem_u32(sm);
    const int tid = threadIdx.x, lane = tid & 31, wid = tid >> 5;
    const int wm = wid >> 2, wn = wid & 3;
    const int m0 = blockIdx.y * 128, n0 = blockIdx.x * 128;
    const long long bz = blockIdx.z;
    const int sel = blockIdx.y >> 1;          // 0=k, 1=q
    const int mloc0 = m0 - sel * 256;

    const __half* A = wh + W2S + (long long)m0 * 256;
    const __half* B = ((sel == 0) ? hk : hq) + bz * (4096LL * 256)
                    + (long long)n0 * 256;

    GEMM_MAINLOOP(A, 256, B, 256, 256)

    const int g = lane >> 2, q4 = lane & 3;
    const float* bias = (sel == 0) ? kb  : qb;
    const float* gam  = (sel == 0) ? kg  : qg;
    const float* bet  = (sel == 0) ? kbe : qbe;
    const float* mu   = (sel == 0) ? kmu : qmu;
    const float* var  = (sel == 0) ? kvr : qvr;
    __half* out = ((sel == 0) ? Kt : Qt) + bz * (4096LL * 256);

#pragma unroll
    for (int i = 0; i < 4; ++i) {
        const int mA = mloc0 + wm * 64 + i * 16 + g;
        const int mB = mA + 8;
        const float bA = bias[mA], bB = bias[mB];
        const float sA = gam[mA] * rsqrtf(var[mA] + EPSV);
        const float tA = bet[mA] - mu[mA] * sA;
        const float sB = gam[mB] * rsqrtf(var[mB] + EPSV);
        const float tB = bet[mB] - mu[mB] * sB;
#pragma unroll
        for (int j = 0; j < 4; ++j) {
            const int col = n0 + wn * 32 + j * 8 + q4 * 2;
            float v00 = fmaxf(fmaf(acc[i][j][0] + bA, sA, tA), 0.f);
            float v01 = fmaxf(fmaf(acc[i][j][1] + bA, sA, tA), 0.f);
            float v10 = fmaxf(fmaf(acc[i][j][2] + bB, sB, tB), 0.f);
            float v11 = fmaxf(fmaf(acc[i][j][3] + bB, sB, tB), 0.f);
            out[(long long)col * 256 + mA]       = __float2half_rn(v00);
            out[(long long)(col + 1) * 256 + mA] = __float2half_rn(v01);
            out[(long long)col * 256 + mB]       = __float2half_rn(v10);
            out[(long long)(col + 1) * 256 + mB] = __float2half_rn(v11);
        }
    }
}

// ---------------------------------------------------------------------------
// out projection: out[co][n] = o_w . ctx + o_b  (fp32 out)
// ---------------------------------------------------------------------------
__global__ void __launch_bounds__(256, 2)
outp_kernel(const __half* __restrict__ wh, const __half* __restrict__ ctx,
            float* __restrict__ out, const float* __restrict__ bias)
{
    extern __shared__ char sm[];
    const uint32_t sb = smem_u32(sm);
    const int tid = threadIdx.x, lane = tid & 31, wid = tid >> 5;
    const int wm = wid >> 2, wn = wid & 3;
    const int m0 = blockIdx.y * 128, n0 = blockIdx.x * 128;
    const long long bz = blockIdx.z;

    const __half* A = wh + WOW + (long long)m0 * 256;
    const __half* B = ctx + bz * (4096LL * 256) + (long long)n0 * 256;

    GEMM_MAINLOOP(A, 256, B, 256, 256)

    const int g = lane >> 2, q4 = lane & 3;
    float* og = out + bz * (512LL * 4096);
#pragma unroll
    for (int i = 0; i < 4; ++i) {
        const int mA = m0 + wm * 64 + i * 16 + g;
        const int mB = mA + 8;
        const float bA = bias[mA], bB = bias[mB];
#pragma unroll
        for (int j = 0; j < 4; ++j) {
            const int col = n0 + wn * 32 + j * 8 + q4 * 2;
            *(float2*)&og[(long long)mA * 4096 + col] =
                make_float2(acc[i][j][0] + bA, acc[i][j][1] + bA);
            *(float2*)&og[(long long)mB * 4096 + col] =
                make_float2(acc[i][j][2] + bB, acc[i][j][3] + bB);
        }
    }
}

// ---------------------------------------------------------------------------
// Fused attention (R12/R14-proven config): 128 queries/CTA, 256 threads,
// 8 x 32-wide K chunks + 4 V chunks per key tile, 4-slot cp.async ring.
// SMEM: Q 8x10240 | ring 4x20480 | P 4x10240 | rsum 512 = 205312 B
// ---------------------------------------------------------------------------
#define QS_OFF   0
#define RING_OFF 81920
#define PS_OFF   163840
#define RS_OFF   204800
#define ATT_SMEM 205312

__global__ void __launch_bounds__(256, 1)
attn_fused(const __half* __restrict__ Qt, const __half* __restrict__ Kt,
           const __half* __restrict__ Vf, __half* __restrict__ ctx)
{
    extern __shared__ char sm[];
    const uint32_t sb = smem_u32(sm);

    const int tid = threadIdx.x, lane = tid & 31, wid = tid >> 5;
    const int wm = wid >> 2, wn = wid & 3;
    const int g = lane >> 2, q4 = lane & 3;
    const int n0 = blockIdx.x * 128;
    const long long bz = blockIdx.z;
    const long long sC = 4096LL * 256;

    const __half* Qg = Qt + bz * sC + (long long)n0 * 256;
    const __half* Kg = Kt + bz * sC;
    const __half* Vg = Vf + bz * sC;

    const int crow = tid >> 2, cq = tid & 3;

    float* rsum = (float*)(sm + RS_OFF);
    if (tid < 128) rsum[tid] = 0.f;

    auto issueK = [&](int kt, int c) {
        if (kt >= 32) return;
        const uint32_t st = sb + RING_OFF + (c & 3) * 20480;
        const __half* src = Kg + (long long)(kt * 128) * 256 + c * 32;
#pragma unroll
        for (int i = 0; i < 2; ++i) {
            const int row = i * 64 + crow;
            CP_ASYNC16(st + row * 80 + cq * 16, src + row * 256 + cq * 8);
        }
    };
    auto issueV = [&](int kt, int vc) {
        const uint32_t st = sb + RING_OFF + vc * 20480;
        const __half* src = Vg + kt * 128 + vc * 32;
#pragma unroll
        for (int i = 0; i < 4; ++i) {
            const int row = i * 64 + crow;
            CP_ASYNC16(st + row * 80 + cq * 16, src + (long long)row * 4096 + cq * 8);
        }
    };

#pragma unroll
    for (int c = 0; c < 8; ++c) {
#pragma unroll
        for (int i = 0; i < 2; ++i) {
            const int row = i * 64 + crow;
            CP_ASYNC16(sb + QS_OFF + c * 10240 + row * 80 + cq * 16,
                       Qg + row * 256 + c * 32 + cq * 8);
        }
    }
    CP_COMMIT();
    issueK(0, 0); CP_COMMIT();
    issueK(0, 1); CP_COMMIT();
    issueK(0, 2); CP_COMMIT();

    const uint32_t aoff  = (wm * 64 + (lane & 15)) * 80 + (lane >> 4) * 16;
    const uint32_t boffK = (wn * 32 + (lane & 7) + ((lane >> 4) << 3)) * 80
                         + ((lane >> 3) & 1) * 16;
    const uint32_t boffV = (wn * 64 + (lane & 7) + ((lane >> 4) << 3)) * 80
                         + ((lane >> 3) & 1) * 16;

    float accO[4][8][4];
#pragma unroll
    for (int i = 0; i < 4; ++i)
#pragma unroll
        for (int j = 0; j < 8; ++j)
#pragma unroll
            for (int r = 0; r < 4; ++r) accO[i][j][r] = 0.f;
    float rs[4][2];
#pragma unroll
    for (int i = 0; i < 4; ++i) { rs[i][0] = 0.f; rs[i][1] = 0.f; }

    for (int kt = 0; kt < 32; ++kt) {
        // ================= phase A: S tile =================
        float accS[4][4][4];
#pragma unroll
        for (int i = 0; i < 4; ++i)
#pragma unroll
            for (int j = 0; j < 4; ++j)
#pragma unroll
                for (int r = 0; r < 4; ++r) accS[i][j][r] = 0.f;

#pragma unroll
        for (int c = 0; c < 8; ++c) {
            CP_WAIT2();
            __syncthreads();
            const uint32_t st = sb + RING_OFF + (c & 3) * 20480;
            const uint32_t qs = sb + QS_OFF + c * 10240;

            uint32_t a0[4][4], b0[4][2];
#pragma unroll
            for (int i = 0; i < 4; ++i)
                ldsm_x4(a0[i][0], a0[i][1], a0[i][2], a0[i][3],
                        qs + aoff + i * 1280);
#pragma unroll
            for (int p = 0; p < 2; ++p) {
                uint32_t t0, t1, t2, t3;
                ldsm_x4(t0, t1, t2, t3, st + boffK + p * 1280);
                b0[2 * p][0] = t0; b0[2 * p][1] = t1;
                b0[2 * p + 1][0] = t2; b0[2 * p + 1][1] = t3;
            }
            if (c < 5) issueK(kt, c + 3); else issueV(kt, c - 5);
            CP_COMMIT();
#pragma unroll
            for (int i = 0; i < 4; ++i)
#pragma unroll
                for (int j = 0; j < 4; ++j)
                    mma_f16(accS[i][j], a0[i], b0[j]);

            uint32_t a1[4][4], b1[4][2];
#pragma unroll
            for (int i = 0; i < 4; ++i)
                ldsm_x4(a1[i][0], a1[i][1], a1[i][2], a1[i][3],
                        qs + aoff + i * 1280 + 32);
#pragma unroll
            for (int p = 0; p < 2; ++p) {
                uint32_t t0, t1, t2, t3;
                ldsm_x4(t0, t1, t2, t3, st + boffK + p * 1280 + 32);
                b1[2 * p][0] = t0; b1[2 * p][1] = t1;
                b1[2 * p + 1][0] = t2; b1[2 * p + 1][1] = t3;
            }
#pragma unroll
            for (int i = 0; i < 4; ++i)
#pragma unroll
                for (int j = 0; j < 4; ++j)
                    mma_f16(accS[i][j], a1[i], b1[j]);
        }

        // ---- exp -> P tile (SMEM), row-sum partials ----
        {
            char* pbase = sm + PS_OFF + wn * 10240;
#pragma unroll
            for (int i = 0; i < 4; ++i) {
                const int rA = wm * 64 + i * 16 + g;
                float sA = 0.f, sB = 0.f;
#pragma unroll
                for (int j = 0; j < 4; ++j) {
                    float v00 = ex2f(fmaf(accS[i][j][0], EXP_C1, EXP_C0));
                    float v01 = ex2f(fmaf(accS[i][j][1], EXP_C1, EXP_C0));
                    float v10 = ex2f(fmaf(accS[i][j][2], EXP_C1, EXP_C0));
                    float v11 = ex2f(fmaf(accS[i][j][3], EXP_C1, EXP_C0));
                    sA += v00 + v01; sB += v10 + v11;
                    const int bofs = j * 16 + q4 * 4;
                    *(__half2*)(pbase + rA * 80 + bofs)       = __floats2half2_rn(v00, v01);
                    *(__half2*)(pbase + (rA + 8) * 80 + bofs) = __floats2half2_rn(v10, v11);
                }
                rs[i][0] += sA; rs[i][1] += sB;
            }
        }

        // ================= phase B: accO += P . V^T =================
#pragma unroll
        for (int vc = 0; vc < 4; ++vc) {
            CP_WAIT2();
            __syncthreads();
            const uint32_t st = sb + RING_OFF + vc * 20480;
            const uint32_t ps = sb + PS_OFF + vc * 10240;

            uint32_t a0[4][4], b0[8][2];
#pragma unroll
            for (int i = 0; i < 4; ++i)
                ldsm_x4(a0[i][0], a0[i][1], a0[i][2], a0[i][3],
                        ps + aoff + i * 1280);
#pragma unroll
            for (int p = 0; p < 4; ++p) {
                uint32_t t0, t1, t2, t3;
                ldsm_x4(t0, t1, t2, t3, st + boffV + p * 1280);
                b0[2 * p][0] = t0; b0[2 * p][1] = t1;
                b0[2 * p + 1][0] = t2; b0[2 * p + 1][1] = t3;
            }
            if (vc == 0) issueV(kt, 3); else issueK(kt + 1, vc - 1);
            CP_COMMIT();
#pragma unroll
            for (int i = 0; i < 4; ++i)
#pragma unroll
                for (int j = 0; j < 8; ++j)
                    mma_f16(accO[i][j], a0[i], b0[j]);

            uint32_t a1[4][4], b1[8][2];
#pragma unroll
            for (int i = 0; i < 4; ++i)
                ldsm_x4(a1[i][0], a1[i][1], a1[i][2], a1[i][3],
                        ps + aoff + i * 1280 + 32);
#pragma unroll
            for (int p = 0; p < 4; ++p) {
                uint32_t t0, t1, t2, t3;
                ldsm_x4(t0, t1, t2, t3, st + boffV + p * 1280 + 32);
                b1[2 * p][0] = t0; b1[2 * p][1] = t1;
                b1[2 * p + 1][0] = t2; b1[2 * p + 1][1] = t3;
            }
#pragma unroll
            for (int i = 0; i < 4; ++i)
#pragma unroll
                for (int j = 0; j < 8; ++j)
                    mma_f16(accO[i][j], a1[i], b1[j]);
        }
    }

    // ---- row-sum reduce across warps ----
#pragma unroll
    for (int i = 0; i < 4; ++i) {
        float sA = rs[i][0], sB = rs[i][1];
        sA += __shfl_xor_sync(0xffffffffu, sA, 1);
        sA += __shfl_xor_sync(0xffffffffu, sA, 2);
        sB += __shfl_xor_sync(0xffffffffu, sB, 1);
        sB += __shfl_xor_sync(0xffffffffu, sB, 2);
        if (q4 == 0) {
            atomicAdd(&rsum[wm * 64 + i * 16 + g], sA);
            atomicAdd(&rsum[wm * 64 + i * 16 + g + 8], sB);
        }
    }
    __syncthreads();

    // ---- normalize + store ctx [n][c] ----
    __half* cg = ctx + (bz * 4096 + n0) * 256;
#pragma unroll
    for (int i = 0; i < 4; ++i) {
        const int rA = wm * 64 + i * 16 + g;
        const float iA = 1.f / rsum[rA];
        const float iB = 1.f / rsum[rA + 8];
#pragma unroll
        for (int j = 0; j < 8; ++j) {
            const int col = wn * 64 + j * 8 + q4 * 2;
            *(__half2*)&cg[(long long)rA * 256 + col] =
                __floats2half2_rn(accO[i][j][0] * iA, accO[i][j][1] * iA);
            *(__half2*)&cg[(long long)(rA + 8) * 256 + col] =
                __floats2half2_rn(accO[i][j][2] * iB, accO[i][j][3] * iB);
        }
    }
}

// ---------------------------------------------------------------------------
extern "C" void kernel_launch(void* const* d_in, const int* in_sizes, int n_in,
                              void* d_out, int out_size)
{
    const float* x     = (const float*)d_in[0];
    const float* k_w1  = (const float*)d_in[1];
    const float* k_b1  = (const float*)d_in[2];
    const float* k_g1  = (const float*)d_in[3];
    const float* k_be1 = (const float*)d_in[4];
    const float* k_m1  = (const float*)d_in[5];
    const float* k_v1  = (const float*)d_in[6];
    const float* k_w2  = (const float*)d_in[7];
    const float* k_b2  = (const float*)d_in[8];
    const float* k_g2  = (const float*)d_in[9];
    const float* k_be2 = (const float*)d_in[10];
    const float* k_m2  = (const float*)d_in[11];
    const float* k_v2  = (const float*)d_in[12];
    const float* q_w1  = (const float*)d_in[13];
    const float* q_b1  = (const float*)d_in[14];
    const float* q_g1  = (const float*)d_in[15];
    const float* q_be1 = (const float*)d_in[16];
    const float* q_m1  = (const float*)d_in[17];
    const float* q_v1  = (const float*)d_in[18];
    const float* q_w2  = (const float*)d_in[19];
    const float* q_b2  = (const float*)d_in[20];
    const float* q_g2  = (const float*)d_in[21];
    const float* q_be2 = (const float*)d_in[22];
    const float* q_m2  = (const float*)d_in[23];
    const float* q_v2  = (const float*)d_in[24];
    const float* v_w   = (const float*)d_in[25];
    const float* v_b   = (const float*)d_in[26];
    const float* o_w   = (const float*)d_in[27];
    const float* o_b   = (const float*)d_in[28];

    void *xT_, *wh_, *hk_, *hq_, *Kt_, *Qt_, *V_, *ctx_;
    cudaGetSymbolAddress(&xT_,  g_xT);
    cudaGetSymbolAddress(&wh_,  g_wh);
    cudaGetSymbolAddress(&hk_,  g_hk);
    cudaGetSymbolAddress(&hq_,  g_hq);
    cudaGetSymbolAddress(&Kt_,  g_K);
    cudaGetSymbolAddress(&Qt_,  g_Q);
    cudaGetSymbolAddress(&V_,   g_V);
    cudaGetSymbolAddress(&ctx_, g_ctx);
    __half* xT  = (__half*)xT_;
    __half* wh  = (__half*)wh_;
    __half* hk  = (__half*)hk_;
    __half* hq  = (__half*)hq_;
    __half* Kt  = (__half*)Kt_;
    __half* Qt  = (__half*)Qt_;
    __half* V   = (__half*)V_;
    __half* ctx = (__half*)ctx_;

    const int GSM = 81920;
    cudaFuncSetAttribute(proj1_kernel, cudaFuncAttributeMaxDynamicSharedMemorySize, GSM);
    cudaFuncSetAttribute(proj2_kernel, cudaFuncAttributeMaxDynamicSharedMemorySize, GSM);
    cudaFuncSetAttribute(outp_kernel,  cudaFuncAttributeMaxDynamicSharedMemorySize, GSM);
    cudaFuncSetAttribute(attn_fused,   cudaFuncAttributeMaxDynamicSharedMemorySize, ATT_SMEM);

    // ---- preprocessing ----
    wconv_kernel<<<640, 256>>>(k_w1, k_w2, q_w1, q_w2, v_w, o_w, wh);
    xT_kernel<<<dim3(128, 16, 4), dim3(32, 8)>>>(x, xT);

    // ---- stage 1: h_k, h_q, V in ONE launch ----
    proj1_kernel<<<dim3(32, 6, 4), 256, GSM>>>(
        wh, xT, hk, hq, V,
        k_b1, k_g1, k_be1, k_m1, k_v1,
        q_b1, q_g1, q_be1, q_m1, q_v1,
        v_b);
    // ---- stage 2: Kt, Qt in ONE launch ----
    proj2_kernel<<<dim3(32, 4, 4), 256, GSM>>>(
        wh, hk, hq, Kt, Qt,
        k_b2, k_g2, k_be2, k_m2, k_v2,
        q_b2, q_g2, q_be2, q_m2, q_v2);
    // ---- fused attention ----
    attn_fused<<<dim3(32, 1, 4), 256, ATT_SMEM>>>(Qt, Kt, V, ctx);
    // ---- output projection ----
    outp_kernel<<<dim3(32, 4, 4), 256, GSM>>>(wh, ctx, (float*)d_out, o_b);
}